// round 14
// baseline (speedup 1.0000x reference)
#include <cuda_runtime.h>
#include <cuda_fp16.h>
#include <cstdint>

// Problem shape: B=4, S=4096, E=1024, H=16, D=64
#define M_TOT 16384
#define N_TOT 1024
#define K_TOT 1024

// ---------------- static device scratch ----------------
__device__ __half g_qkvh[3][(size_t)M_TOT * N_TOT];        // 96 MB (fp16 q,k,v)
__device__ __half g_xb[(size_t)M_TOT * K_TOT];             // blocked+swizzled fp16 x
__device__ __half g_wb[3][(size_t)K_TOT * N_TOT];          // blocked+swizzled fp16 W^T
__device__ int g_cnt[64];                                  // per-m-block gemm tile completion
__device__ int g_xcnt[64];                                 // per-m-block x-convert completion (4 items)
__device__ int g_wcnt;                                     // W-convert completion (1536 items)
__device__ int g_conv_ctr;                                 // convert work-stealing counter
__device__ int g_attn_ctr;                                 // attn work-stealing counter

// ---------------- PTX helpers ----------------
__device__ __forceinline__ uint32_t sptr(const void* p) {
    return (uint32_t)__cvta_generic_to_shared(p);
}
__device__ __forceinline__ void cpa16(uint32_t s, const void* g) {
    asm volatile("cp.async.cg.shared.global [%0], [%1], 16;" :: "r"(s), "l"(g) : "memory");
}
__device__ __forceinline__ void cp_commit() { asm volatile("cp.async.commit_group;" ::: "memory"); }
template <int N> __device__ __forceinline__ void cp_wait() {
    asm volatile("cp.async.wait_group %0;" :: "n"(N) : "memory");
}
__device__ __forceinline__ void mbar_init(uint32_t a, uint32_t cnt) {
    asm volatile("mbarrier.init.shared.b64 [%0], %1;" :: "r"(a), "r"(cnt) : "memory");
}
__device__ __forceinline__ void mbar_expect_tx(uint32_t a, uint32_t bytes) {
    asm volatile("mbarrier.arrive.expect_tx.shared.b64 _, [%0], %1;"
                 :: "r"(a), "r"(bytes) : "memory");
}
__device__ __forceinline__ void mbar_arrive(uint32_t a) {
    asm volatile("mbarrier.arrive.shared.b64 _, [%0];" :: "r"(a) : "memory");
}
__device__ __forceinline__ void mbar_wait(uint32_t a, uint32_t parity) {
    asm volatile(
        "{\n\t.reg .pred P;\n\t"
        "WL%=:\n\t"
        "mbarrier.try_wait.parity.acquire.cta.shared::cta.b64 P, [%0], %1, 0x989680;\n\t"
        "@P bra WD%=;\n\t"
        "bra WL%=;\n\t"
        "WD%=:\n\t}"
        :: "r"(a), "r"(parity) : "memory");
}
__device__ __forceinline__ void bulk_g2s(uint32_t dst, const void* src, uint32_t bytes,
                                         uint32_t mbar) {
    asm volatile(
        "cp.async.bulk.shared::cta.global.mbarrier::complete_tx::bytes [%0], [%1], %2, [%3];"
        :: "r"(dst), "l"(src), "r"(bytes), "r"(mbar) : "memory");
}
__device__ __forceinline__ int ld_acq(const int* p) {
    int v;
    asm volatile("ld.global.acquire.gpu.b32 %0, [%1];" : "=r"(v) : "l"(p));
    return v;
}
__device__ __forceinline__ void ldm_x4(uint32_t& r0, uint32_t& r1, uint32_t& r2, uint32_t& r3,
                                       uint32_t addr) {
    asm volatile("ldmatrix.sync.aligned.m8n8.x4.shared.b16 {%0,%1,%2,%3}, [%4];"
                 : "=r"(r0), "=r"(r1), "=r"(r2), "=r"(r3) : "r"(addr));
}
__device__ __forceinline__ void ldm_x4t(uint32_t& r0, uint32_t& r1, uint32_t& r2, uint32_t& r3,
                                        uint32_t addr) {
    asm volatile("ldmatrix.sync.aligned.m8n8.x4.trans.shared.b16 {%0,%1,%2,%3}, [%4];"
                 : "=r"(r0), "=r"(r1), "=r"(r2), "=r"(r3) : "r"(addr));
}
__device__ __forceinline__ void mma_f16(float* c, const uint32_t* a, const uint32_t* b) {
    asm volatile(
        "mma.sync.aligned.m16n8k16.row.col.f32.f16.f16.f32 "
        "{%0,%1,%2,%3}, {%4,%5,%6,%7}, {%8,%9}, {%0,%1,%2,%3};"
        : "+f"(c[0]), "+f"(c[1]), "+f"(c[2]), "+f"(c[3])
        : "r"(a[0]), "r"(a[1]), "r"(a[2]), "r"(a[3]), "r"(b[0]), "r"(b[1]));
}

#define SWZ(o) ((o) ^ (((o) >> 3) & 0x70))

// ---------------- init kernel: zero counters per graph replay ----------------
__global__ void init_kernel() {
    const int t = threadIdx.x;
    if (t < 64) { g_cnt[t] = 0; g_xcnt[t] = 0; }
    if (t == 64) { g_wcnt = 0; g_conv_ctr = 0; g_attn_ctr = 0; }
}

// ---------------- per-warp attention body (16x64 q,k,v at tb) ----------------
__device__ __forceinline__ void attn_warp(uint32_t tb, int token, int lane,
                                          float* __restrict__ out)
{
    #pragma unroll
    for (int j = 0; j < 12; j++) {
        int idx = lane + j * 32;
        int mat = idx >> 7;
        int rem = idx & 127;
        int r = rem >> 3, c = rem & 7;
        cpa16(tb + (uint32_t)mat * 2048 + SWZ((uint32_t)(r * 128 + c * 16)),
              g_qkvh[mat] + ((size_t)token << 10) + r * 64 + c * 8);
    }
    cp_commit();
    cp_wait<0>();
    __syncwarp();

    const int a_row = ((lane >> 3) & 1) * 8 + (lane & 7);
    const int a_cb = (lane >> 4) * 16;
    const int b_row = ((lane >> 4) & 1) * 8 + (lane & 7);
    const int b_cb = ((lane >> 3) & 1) * 16;
    const int v_row = ((lane >> 3) & 1) * 8 + (lane & 7);
    const int v_cb = (lane >> 4) * 16;

    float attc[2][4] = {{0.f, 0.f, 0.f, 0.f}, {0.f, 0.f, 0.f, 0.f}};
    #pragma unroll
    for (int kc = 0; kc < 4; kc++) {
        uint32_t a[4];
        ldm_x4(a[0], a[1], a[2], a[3], tb + SWZ((uint32_t)(a_row * 128 + kc * 32 + a_cb)));
        uint32_t r0, r1, r2, r3;
        ldm_x4(r0, r1, r2, r3, tb + 2048 + SWZ((uint32_t)(b_row * 128 + kc * 32 + b_cb)));
        uint32_t blo[2] = {r0, r1}, bhi[2] = {r2, r3};
        mma_f16(attc[0], a, blo);
        mma_f16(attc[1], a, bhi);
    }

    uint32_t aa[4];
    {
        __half2 h0 = __floats2half2_rn(attc[0][0], attc[0][1]);
        __half2 h1 = __floats2half2_rn(attc[0][2], attc[0][3]);
        __half2 h2 = __floats2half2_rn(attc[1][0], attc[1][1]);
        __half2 h3 = __floats2half2_rn(attc[1][2], attc[1][3]);
        aa[0] = *(uint32_t*)&h0;
        aa[1] = *(uint32_t*)&h1;
        aa[2] = *(uint32_t*)&h2;
        aa[3] = *(uint32_t*)&h3;
    }

    float* __restrict__ op = out + ((size_t)token << 10);
    const int row = lane >> 2;
    const int cl = (lane & 3) * 2;
    #pragma unroll
    for (int dc = 0; dc < 4; dc++) {
        uint32_t r0, r1, r2, r3;
        ldm_x4t(r0, r1, r2, r3, tb + 4096 + SWZ((uint32_t)(v_row * 128 + dc * 32 + v_cb)));
        uint32_t blo[2] = {r0, r1}, bhi[2] = {r2, r3};
        float oc0[4] = {0.f, 0.f, 0.f, 0.f};
        float oc1[4] = {0.f, 0.f, 0.f, 0.f};
        mma_f16(oc0, aa, blo);
        mma_f16(oc1, aa, bhi);
        float* p = op + row * 64 + dc * 16 + cl;
        *(float2*)(p) = make_float2(oc0[0], oc0[1]);
        *(float2*)(p + 8 * 64) = make_float2(oc0[2], oc0[3]);
        *(float2*)(p + 8) = make_float2(oc1[0], oc1[1]);
        *(float2*)(p + 8 * 64 + 8) = make_float2(oc1[2], oc1[3]);
    }
}

// ---------------- fused convert + GEMM + attention ----------------
static constexpr int STAGE_BYTES = 49152;               // A 32KB + B 16KB
static constexpr uint32_t OFF_B = 32768;
static constexpr int NSTAGE = 4;
static constexpr int SMEM_DYN = NSTAGE * STAGE_BYTES;   // 192 KB
static constexpr int GEMM_GRID = 148;
static constexpr int GEMM_THREADS = 512;
static constexpr int NTILES = 3 * 64 * 8;               // 1536
static constexpr int KT_PER_TILE = 16;
static constexpr int ATTN_GROUPS = M_TOT / 16;          // 1024 groups of 16 tokens
static constexpr int W_ITEMS = 1536;                    // pairs of 32x32 W tiles
static constexpr int X_ITEMS = 256;                     // 64-row quarters of m-blocks
static constexpr int CONV_ITEMS = W_ITEMS + X_ITEMS;

// m-block-major: u = mbk*24 + z*8 + nb  (m-blocks complete early-to-late)
__device__ __forceinline__ void tile_coord(int u, int& z, int& mb, int& nb) {
    mb = u / 24;
    int r = u - mb * 24;
    z = r >> 3;
    nb = r & 7;
}

__global__ __launch_bounds__(GEMM_THREADS, 1)
void qkv_fused(const float* __restrict__ x,
               const float* __restrict__ Wq, const float* __restrict__ Wk,
               const float* __restrict__ Wv,
               const float* __restrict__ bq, const float* __restrict__ bk,
               const float* __restrict__ bv, float* __restrict__ attn_out)
{
    extern __shared__ __align__(128) char dsm[];
    __shared__ __align__(8) unsigned long long full_bar[NSTAGE];
    __shared__ __align__(8) unsigned long long empty_bar[NSTAGE];
    __shared__ int s_item;
    __shared__ int s_group;

    const int tid = threadIdx.x;
    const int lane = tid & 31;
    const int wid = tid >> 5;
    const int warp_m = wid >> 2;
    const int warp_n = wid & 3;
    const int cta = blockIdx.x;

    const uint32_t sbase = sptr(dsm);
    const uint32_t fb0 = sptr(&full_bar[0]);
    const uint32_t eb0 = sptr(&empty_bar[0]);

    if (tid == 0) {
        #pragma unroll
        for (int s = 0; s < NSTAGE; s++) {
            mbar_init(fb0 + s * 8, 1);
            mbar_init(eb0 + s * 8, 16);
        }
    }

    // ===================== Phase 0: convert (work stealing) =====================
    {
        float (*tile)[33] = (float(*)[33])dsm;   // 2 x 32x33 fp32 tiles (8.5 KB)
        while (true) {
            __syncthreads();
            if (tid == 0) s_item = atomicAdd(&g_conv_ctr, 1);
            __syncthreads();
            const int item = s_item;
            if (item >= CONV_ITEMS) break;
            if (item < W_ITEMS) {
                // two adjacent 32x32 W tiles; threads 0-255 -> tile0, 256-511 -> tile1
                const int half = tid >> 8;           // 0..1
                const int tl = tid & 255;
                const int t2 = item * 2 + half;
                const int z = t2 >> 10;
                const int t = t2 & 1023;
                const int k0 = (t >> 5) * 32, n0 = (t & 31) * 32;
                const float* __restrict__ W = (z == 0) ? Wq : (z == 1) ? Wk : Wv;
                const int tx = tl & 31, ty0 = tl >> 5;
                #pragma unroll
                for (int r = 0; r < 4; r++) {
                    int y = ty0 + r * 8;
                    tile[half * 33][0] = tile[half * 33][0];  // no-op keep layout simple
                    tile[half * 32 + y + half][tx] = 0.f;     // placeholder overwritten below
                }
                // use separate regions: tile rows [half*33 .. half*33+31]
                float (*tt)[33] = (float(*)[33])(dsm + half * 33 * 33 * sizeof(float));
                #pragma unroll
                for (int r = 0; r < 4; r++) {
                    int y = ty0 + r * 8;
                    tt[y][tx] = W[(size_t)(k0 + y) * N_TOT + n0 + tx];
                }
                __syncthreads();
                const int k = k0 + tx;
                const int kt = k >> 6;
                #pragma unroll
                for (int r = 0; r < 4; r++) {
                    int y = ty0 + r * 8;
                    const int n = n0 + y;
                    const int nb = n >> 7, rn = n & 127;
                    const uint32_t off = SWZ((uint32_t)(rn * 128 + (k & 63) * 2));
                    char* dst = (char*)g_wb[z] + (((size_t)(nb * 16 + kt)) << 14) + off;
                    *(__half*)dst = __float2half_rn(tt[tx][y]);
                }
                __threadfence();
                __syncthreads();
                if (tid == 0) atomicAdd(&g_wcnt, 1);
            } else {
                const int xi = item - W_ITEMS;
                const int mbk = xi >> 2;
                const int r0 = (xi & 3) * 64;
                #pragma unroll 4
                for (int it = 0; it < 16; it++) {
                    int idx = tid + it * 512;       // 0..8191
                    int r = idx >> 7;               // 0..63
                    int c = idx & 127;              // chunk of 8 k
                    int m = mbk * 256 + r0 + r;
                    int k = c * 8;
                    const float* src = x + (size_t)m * 1024 + k;
                    float4 v0 = *(const float4*)(src);
                    float4 v1 = *(const float4*)(src + 4);
                    union { __half h[8]; uint4 u; } p;
                    p.h[0] = __float2half_rn(v0.x); p.h[1] = __float2half_rn(v0.y);
                    p.h[2] = __float2half_rn(v0.z); p.h[3] = __float2half_rn(v0.w);
                    p.h[4] = __float2half_rn(v1.x); p.h[5] = __float2half_rn(v1.y);
                    p.h[6] = __float2half_rn(v1.z); p.h[7] = __float2half_rn(v1.w);
                    const int kt = k >> 6;
                    const uint32_t off = SWZ((uint32_t)((r0 + r) * 128 + (k & 63) * 2));
                    char* dst = (char*)g_xb + (((size_t)(mbk * 16 + kt)) << 15) + off;
                    *(uint4*)dst = p.u;
                }
                __threadfence();
                __syncthreads();
                if (tid == 0) atomicAdd(&g_xcnt[mbk], 1);
            }
        }
    }
    __syncthreads();   // dsm free; convert done for this CTA

    const int my_ntiles = (NTILES - cta + GEMM_GRID - 1) / GEMM_GRID;
    const int total = my_ntiles * KT_PER_TILE;

    float acc[4][4][4];
    #pragma unroll
    for (int mi = 0; mi < 4; mi++)
        #pragma unroll
        for (int ni = 0; ni < 4; ni++)
            #pragma unroll
            for (int r = 0; r < 4; r++) acc[mi][ni][r] = 0.f;

    const int a_row = warp_m * 64 + ((lane >> 3) & 1) * 8 + (lane & 7);
    const int a_cb0 = (lane >> 4) * 16;
    const int b_row = warp_n * 32 + ((lane >> 4) & 1) * 8 + (lane & 7);
    const int b_cb0 = ((lane >> 3) & 1) * 16;

    auto issue = [&](int g) {
        const int slot = g & 3;
        int u = cta + (g >> 4) * GEMM_GRID;
        int z, mbk, nbk;
        tile_coord(u, z, mbk, nbk);
        const int kt = g & 15;
        // gate on x conversion of this m-block
        while (ld_acq(&g_xcnt[mbk]) < 4) __nanosleep(64);
        const uint32_t fb_s = fb0 + slot * 8;
        const uint32_t sb = sbase + (uint32_t)slot * STAGE_BYTES;
        mbar_expect_tx(fb_s, STAGE_BYTES);
        bulk_g2s(sb, (const char*)g_xb + (((size_t)(mbk * 16 + kt)) << 15), 32768, fb_s);
        bulk_g2s(sb + OFF_B, (const char*)g_wb[z] + (((size_t)(nbk * 16 + kt)) << 14), 16384, fb_s);
    };

    if (tid == 0) {
        while (ld_acq(&g_wcnt) < W_ITEMS) __nanosleep(64);   // all W converted
        #pragma unroll
        for (int g = 0; g < 3; g++) if (g < total) issue(g);
    }

    // ===================== GEMM phase =====================
    for (int g = 0; g < total; ++g) {
        mbar_wait(fb0 + (g & 3) * 8, (g >> 2) & 1);
        if (tid == 0 && g + 3 < total) {
            const int gp = g + 3;
            if (gp >= NSTAGE) mbar_wait(eb0 + (gp & 3) * 8, ((gp >> 2) - 1) & 1);
            issue(gp);
        }

        const uint32_t abase = sbase + (uint32_t)(g & 3) * STAGE_BYTES;

        #pragma unroll
        for (int ks = 0; ks < 4; ks++) {
            uint32_t a[4][4], b[4][2];
            #pragma unroll
            for (int mi = 0; mi < 4; mi++) {
                uint32_t off = (uint32_t)((a_row + mi * 16) * 128 + ks * 32 + a_cb0);
                ldm_x4(a[mi][0], a[mi][1], a[mi][2], a[mi][3], abase + SWZ(off));
            }
            #pragma unroll
            for (int pr = 0; pr < 2; pr++) {
                uint32_t off = (uint32_t)((b_row + pr * 16) * 128 + ks * 32 + b_cb0);
                uint32_t r0, r1, r2, r3;
                ldm_x4(r0, r1, r2, r3, abase + OFF_B + SWZ(off));
                b[pr * 2 + 0][0] = r0; b[pr * 2 + 0][1] = r1;
                b[pr * 2 + 1][0] = r2; b[pr * 2 + 1][1] = r3;
            }
            #pragma unroll
            for (int mi = 0; mi < 4; mi++)
                #pragma unroll
                for (int ni = 0; ni < 4; ni++)
                    mma_f16(acc[mi][ni], a[mi], b[ni]);
        }

        if (lane == 0) mbar_arrive(eb0 + (g & 3) * 8);

        if ((g & 15) == 15) {
            int u = cta + (g >> 4) * GEMM_GRID;
            int z, mbk, nbk;
            tile_coord(u, z, mbk, nbk);
            const int m0 = mbk * 256, n0 = nbk * 128;
            const float* __restrict__ bias = (z == 0) ? bq : (z == 1) ? bk : bv;
            __half* __restrict__ out = g_qkvh[z];
            const int row_base = m0 + warp_m * 64 + (lane >> 2);
            const int col_loc = warp_n * 32 + (lane & 3) * 2;
            #pragma unroll
            for (int mi = 0; mi < 4; mi++) {
                #pragma unroll
                for (int ni = 0; ni < 4; ni++) {
                    const int col = col_loc + ni * 8;
                    const float b0 = __ldg(bias + n0 + col);
                    const float b1 = __ldg(bias + n0 + col + 1);
                    __half* p0 = out + (size_t)(row_base + mi * 16) * N_TOT + n0 + col;
                    __half* p1 = p0 + 8 * N_TOT;
                    *(__half2*)p0 = __floats2half2_rn(acc[mi][ni][0] + b0, acc[mi][ni][1] + b1);
                    *(__half2*)p1 = __floats2half2_rn(acc[mi][ni][2] + b0, acc[mi][ni][3] + b1);
                    #pragma unroll
                    for (int r = 0; r < 4; r++) acc[mi][ni][r] = 0.f;
                }
            }
            __threadfence();
            __syncthreads();
            if (tid == 0) atomicAdd(&g_cnt[mbk], 1);
        }
    }

    // ===================== attention phase (work stealing) =====================
    __syncthreads();
    while (true) {
        if (tid == 0) s_group = atomicAdd(&g_attn_ctr, 1);
        __syncthreads();
        const int w = s_group;
        if (w >= ATTN_GROUPS) break;
        const int mbk = w >> 4;
        if (tid == 0) {
            while (ld_acq(&g_cnt[mbk]) < 24) __nanosleep(128);
        }
        __syncthreads();
        attn_warp(sbase + (uint32_t)wid * 6144, w * 16 + wid, lane, attn_out);
        __syncthreads();
    }
}

extern "C" void kernel_launch(void* const* d_in, const int* in_sizes, int n_in,
                              void* d_out, int out_size)
{
    const float* x  = (const float*)d_in[0];
    const float* Wq = (const float*)d_in[1];
    const float* bq = (const float*)d_in[2];
    const float* Wk = (const float*)d_in[3];
    const float* bk = (const float*)d_in[4];
    const float* Wv = (const float*)d_in[5];
    const float* bv = (const float*)d_in[6];
    float* out = (float*)d_out;

    init_kernel<<<1, 128>>>();

    cudaFuncSetAttribute(qkv_fused, cudaFuncAttributeMaxDynamicSharedMemorySize, SMEM_DYN);
    qkv_fused<<<GEMM_GRID, GEMM_THREADS, SMEM_DYN>>>(x, Wq, Wk, Wv, bq, bk, bv, out);
}

// round 15
// speedup vs baseline: 1.1145x; 1.1145x over previous
#include <cuda_runtime.h>
#include <cuda_fp16.h>
#include <cstdint>

// Problem shape: B=4, S=4096, E=1024, H=16, D=64
#define M_TOT 16384
#define N_TOT 1024
#define K_TOT 1024

// ---------------- static device scratch ----------------
__device__ __half g_qkvh[3][(size_t)M_TOT * N_TOT];        // 96 MB (fp16 q,k,v)
__device__ __half g_xb[(size_t)M_TOT * K_TOT];             // blocked+swizzled fp16 x
__device__ __half g_wb[3][(size_t)K_TOT * N_TOT];          // blocked+swizzled fp16 W^T
__device__ int g_cnt[64];                                  // per-m-block tile completion
__device__ int g_attn_ctr;                                 // attn work-stealing counter

// ---------------- PTX helpers ----------------
__device__ __forceinline__ uint32_t sptr(const void* p) {
    return (uint32_t)__cvta_generic_to_shared(p);
}
__device__ __forceinline__ void cpa16(uint32_t s, const void* g) {
    asm volatile("cp.async.cg.shared.global [%0], [%1], 16;" :: "r"(s), "l"(g) : "memory");
}
__device__ __forceinline__ void cp_commit() { asm volatile("cp.async.commit_group;" ::: "memory"); }
template <int N> __device__ __forceinline__ void cp_wait() {
    asm volatile("cp.async.wait_group %0;" :: "n"(N) : "memory");
}
__device__ __forceinline__ void mbar_init(uint32_t a, uint32_t cnt) {
    asm volatile("mbarrier.init.shared.b64 [%0], %1;" :: "r"(a), "r"(cnt) : "memory");
}
__device__ __forceinline__ void mbar_expect_tx(uint32_t a, uint32_t bytes) {
    asm volatile("mbarrier.arrive.expect_tx.shared.b64 _, [%0], %1;"
                 :: "r"(a), "r"(bytes) : "memory");
}
__device__ __forceinline__ void mbar_arrive(uint32_t a) {
    asm volatile("mbarrier.arrive.shared.b64 _, [%0];" :: "r"(a) : "memory");
}
__device__ __forceinline__ void mbar_wait(uint32_t a, uint32_t parity) {
    asm volatile(
        "{\n\t.reg .pred P;\n\t"
        "WL%=:\n\t"
        "mbarrier.try_wait.parity.acquire.cta.shared::cta.b64 P, [%0], %1, 0x989680;\n\t"
        "@P bra WD%=;\n\t"
        "bra WL%=;\n\t"
        "WD%=:\n\t}"
        :: "r"(a), "r"(parity) : "memory");
}
__device__ __forceinline__ void bulk_g2s(uint32_t dst, const void* src, uint32_t bytes,
                                         uint32_t mbar) {
    asm volatile(
        "cp.async.bulk.shared::cta.global.mbarrier::complete_tx::bytes [%0], [%1], %2, [%3];"
        :: "r"(dst), "l"(src), "r"(bytes), "r"(mbar) : "memory");
}
__device__ __forceinline__ int ld_acq(const int* p) {
    int v;
    asm volatile("ld.global.acquire.gpu.b32 %0, [%1];" : "=r"(v) : "l"(p));
    return v;
}
__device__ __forceinline__ void ldm_x4(uint32_t& r0, uint32_t& r1, uint32_t& r2, uint32_t& r3,
                                       uint32_t addr) {
    asm volatile("ldmatrix.sync.aligned.m8n8.x4.shared.b16 {%0,%1,%2,%3}, [%4];"
                 : "=r"(r0), "=r"(r1), "=r"(r2), "=r"(r3) : "r"(addr));
}
__device__ __forceinline__ void ldm_x4t(uint32_t& r0, uint32_t& r1, uint32_t& r2, uint32_t& r3,
                                        uint32_t addr) {
    asm volatile("ldmatrix.sync.aligned.m8n8.x4.trans.shared.b16 {%0,%1,%2,%3}, [%4];"
                 : "=r"(r0), "=r"(r1), "=r"(r2), "=r"(r3) : "r"(addr));
}
__device__ __forceinline__ void mma_f16(float* c, const uint32_t* a, const uint32_t* b) {
    asm volatile(
        "mma.sync.aligned.m16n8k16.row.col.f32.f16.f16.f32 "
        "{%0,%1,%2,%3}, {%4,%5,%6,%7}, {%8,%9}, {%0,%1,%2,%3};"
        : "+f"(c[0]), "+f"(c[1]), "+f"(c[2]), "+f"(c[3])
        : "r"(a[0]), "r"(a[1]), "r"(a[2]), "r"(a[3]), "r"(b[0]), "r"(b[1]));
}

#define SWZ(o) ((o) ^ (((o) >> 3) & 0x70))

// ---------------- combined convert kernel (also zeroes flags + counter) ----------------
__global__ __launch_bounds__(256)
void convert_kernel(const float* __restrict__ x,
                    const float* __restrict__ Wq, const float* __restrict__ Wk,
                    const float* __restrict__ Wv)
{
    const int b = blockIdx.x;
    const int tid = threadIdx.x;
    if (b == 0) {
        if (tid < 64) g_cnt[tid] = 0;
        if (tid == 64) g_attn_ctr = 0;
    }
    if (b < 8192) {
        size_t i = ((size_t)b * 256 + tid) * 8;
        const int m = (int)(i >> 10);
        const int k = (int)(i & 1023);
        float4 v0 = *(const float4*)(x + i);
        float4 v1 = *(const float4*)(x + i + 4);
        union { __half h[8]; uint4 u; } p;
        p.h[0] = __float2half_rn(v0.x); p.h[1] = __float2half_rn(v0.y);
        p.h[2] = __float2half_rn(v0.z); p.h[3] = __float2half_rn(v0.w);
        p.h[4] = __float2half_rn(v1.x); p.h[5] = __float2half_rn(v1.y);
        p.h[6] = __float2half_rn(v1.z); p.h[7] = __float2half_rn(v1.w);
        const int mb = m >> 8, r = m & 255;
        const int kt = k >> 6;
        const uint32_t off = SWZ((uint32_t)(r * 128 + (k & 63) * 2));
        char* dst = (char*)g_xb + (((size_t)(mb * 16 + kt)) << 15) + off;
        *(uint4*)dst = p.u;
    } else {
        const int wb = b - 8192;
        const int z = wb >> 10;
        const int t = wb & 1023;
        const int k0 = (t >> 5) * 32, n0 = (t & 31) * 32;
        const float* __restrict__ W = (z == 0) ? Wq : (z == 1) ? Wk : Wv;
        __shared__ float tile[32][33];
        const int tx = tid & 31, ty0 = tid >> 5;
        #pragma unroll
        for (int r = 0; r < 4; r++) {
            int y = ty0 + r * 8;
            tile[y][tx] = W[(size_t)(k0 + y) * N_TOT + n0 + tx];
        }
        __syncthreads();
        const int k = k0 + tx;
        const int kt = k >> 6;
        #pragma unroll
        for (int r = 0; r < 4; r++) {
            int y = ty0 + r * 8;
            const int n = n0 + y;
            const int nb = n >> 7, rn = n & 127;
            const uint32_t off = SWZ((uint32_t)(rn * 128 + (k & 63) * 2));
            char* dst = (char*)g_wb[z] + (((size_t)(nb * 16 + kt)) << 14) + off;
            *(__half*)dst = __float2half_rn(tile[tx][y]);
        }
    }
}

// ---------------- per-warp attention compute (data already in smem at tb) ----------------
__device__ __forceinline__ void attn_compute(uint32_t tb, int token, int lane,
                                             float* __restrict__ out)
{
    const int a_row = ((lane >> 3) & 1) * 8 + (lane & 7);
    const int a_cb = (lane >> 4) * 16;
    const int b_row = ((lane >> 4) & 1) * 8 + (lane & 7);
    const int b_cb = ((lane >> 3) & 1) * 16;
    const int v_row = ((lane >> 3) & 1) * 8 + (lane & 7);
    const int v_cb = (lane >> 4) * 16;

    float attc[2][4] = {{0.f, 0.f, 0.f, 0.f}, {0.f, 0.f, 0.f, 0.f}};
    #pragma unroll
    for (int kc = 0; kc < 4; kc++) {
        uint32_t a[4];
        ldm_x4(a[0], a[1], a[2], a[3], tb + SWZ((uint32_t)(a_row * 128 + kc * 32 + a_cb)));
        uint32_t r0, r1, r2, r3;
        ldm_x4(r0, r1, r2, r3, tb + 2048 + SWZ((uint32_t)(b_row * 128 + kc * 32 + b_cb)));
        uint32_t blo[2] = {r0, r1}, bhi[2] = {r2, r3};
        mma_f16(attc[0], a, blo);
        mma_f16(attc[1], a, bhi);
    }

    uint32_t aa[4];
    {
        __half2 h0 = __floats2half2_rn(attc[0][0], attc[0][1]);
        __half2 h1 = __floats2half2_rn(attc[0][2], attc[0][3]);
        __half2 h2 = __floats2half2_rn(attc[1][0], attc[1][1]);
        __half2 h3 = __floats2half2_rn(attc[1][2], attc[1][3]);
        aa[0] = *(uint32_t*)&h0;
        aa[1] = *(uint32_t*)&h1;
        aa[2] = *(uint32_t*)&h2;
        aa[3] = *(uint32_t*)&h3;
    }

    float* __restrict__ op = out + ((size_t)token << 10);
    const int row = lane >> 2;
    const int cl = (lane & 3) * 2;
    #pragma unroll
    for (int dc = 0; dc < 4; dc++) {
        uint32_t r0, r1, r2, r3;
        ldm_x4t(r0, r1, r2, r3, tb + 4096 + SWZ((uint32_t)(v_row * 128 + dc * 32 + v_cb)));
        uint32_t blo[2] = {r0, r1}, bhi[2] = {r2, r3};
        float oc0[4] = {0.f, 0.f, 0.f, 0.f};
        float oc1[4] = {0.f, 0.f, 0.f, 0.f};
        mma_f16(oc0, aa, blo);
        mma_f16(oc1, aa, bhi);
        float* p = op + row * 64 + dc * 16 + cl;
        *(float2*)(p) = make_float2(oc0[0], oc0[1]);
        *(float2*)(p + 8 * 64) = make_float2(oc0[2], oc0[3]);
        *(float2*)(p + 8) = make_float2(oc1[0], oc1[1]);
        *(float2*)(p + 8 * 64 + 8) = make_float2(oc1[2], oc1[3]);
    }
}

__device__ __forceinline__ void attn_load(uint32_t tb, int token, int lane) {
    #pragma unroll
    for (int j = 0; j < 12; j++) {
        int idx = lane + j * 32;
        int mat = idx >> 7;
        int rem = idx & 127;
        int r = rem >> 3, c = rem & 7;
        cpa16(tb + (uint32_t)mat * 2048 + SWZ((uint32_t)(r * 128 + c * 16)),
              g_qkvh[mat] + ((size_t)token << 10) + r * 64 + c * 8);
    }
}

// ---------------- fused persistent GEMM + work-stealing attention ----------------
static constexpr int STAGE_BYTES = 49152;               // A 32KB + B 16KB
static constexpr uint32_t OFF_B = 32768;
static constexpr int NSTAGE = 4;
static constexpr int SMEM_DYN = NSTAGE * STAGE_BYTES;   // 192 KB
static constexpr int GEMM_GRID = 148;
static constexpr int GEMM_THREADS = 512;
static constexpr int NTILES = 3 * 64 * 8;               // 1536
static constexpr int KT_PER_TILE = 16;
static constexpr int ATTN_GROUPS = M_TOT / 32;          // 512 groups of 32 tokens

// m-block-major: u = mbk*24 + z*8 + nb  (m-blocks complete early-to-late)
__device__ __forceinline__ void tile_coord(int u, int& z, int& mb, int& nb) {
    mb = u / 24;
    int r = u - mb * 24;
    z = r >> 3;
    nb = r & 7;
}

__global__ __launch_bounds__(GEMM_THREADS, 1)
void qkv_fused(const float* __restrict__ bq, const float* __restrict__ bk,
               const float* __restrict__ bv, float* __restrict__ attn_out)
{
    extern __shared__ __align__(128) char dsm[];
    __shared__ __align__(8) unsigned long long full_bar[NSTAGE];
    __shared__ __align__(8) unsigned long long empty_bar[NSTAGE];
    __shared__ int s_group;

    const int tid = threadIdx.x;
    const int lane = tid & 31;
    const int wid = tid >> 5;
    const int warp_m = wid >> 2;
    const int warp_n = wid & 3;
    const int cta = blockIdx.x;

    const int my_ntiles = (NTILES - cta + GEMM_GRID - 1) / GEMM_GRID;
    const int total = my_ntiles * KT_PER_TILE;

    const uint32_t sbase = sptr(dsm);
    const uint32_t fb0 = sptr(&full_bar[0]);
    const uint32_t eb0 = sptr(&empty_bar[0]);

    if (tid == 0) {
        #pragma unroll
        for (int s = 0; s < NSTAGE; s++) {
            mbar_init(fb0 + s * 8, 1);
            mbar_init(eb0 + s * 8, 16);
        }
    }
    __syncthreads();

    float acc[4][4][4];
    #pragma unroll
    for (int mi = 0; mi < 4; mi++)
        #pragma unroll
        for (int ni = 0; ni < 4; ni++)
            #pragma unroll
            for (int r = 0; r < 4; r++) acc[mi][ni][r] = 0.f;

    const int a_row = warp_m * 64 + ((lane >> 3) & 1) * 8 + (lane & 7);
    const int a_cb0 = (lane >> 4) * 16;
    const int b_row = warp_n * 32 + ((lane >> 4) & 1) * 8 + (lane & 7);
    const int b_cb0 = ((lane >> 3) & 1) * 16;

    auto issue = [&](int g) {
        const int slot = g & 3;
        int u = cta + (g >> 4) * GEMM_GRID;
        int z, mbk, nbk;
        tile_coord(u, z, mbk, nbk);
        const int kt = g & 15;
        const uint32_t fb_s = fb0 + slot * 8;
        const uint32_t sb = sbase + (uint32_t)slot * STAGE_BYTES;
        mbar_expect_tx(fb_s, STAGE_BYTES);
        bulk_g2s(sb, (const char*)g_xb + (((size_t)(mbk * 16 + kt)) << 15), 32768, fb_s);
        bulk_g2s(sb + OFF_B, (const char*)g_wb[z] + (((size_t)(nbk * 16 + kt)) << 14), 16384, fb_s);
    };

    if (tid == 0) {
        #pragma unroll
        for (int g = 0; g < 3; g++) if (g < total) issue(g);
    }

    // ===================== GEMM phase =====================
    for (int g = 0; g < total; ++g) {
        mbar_wait(fb0 + (g & 3) * 8, (g >> 2) & 1);
        if (tid == 0 && g + 3 < total) {
            const int gp = g + 3;
            if (gp >= NSTAGE) mbar_wait(eb0 + (gp & 3) * 8, ((gp >> 2) - 1) & 1);
            issue(gp);
        }

        const uint32_t abase = sbase + (uint32_t)(g & 3) * STAGE_BYTES;

        #pragma unroll
        for (int ks = 0; ks < 4; ks++) {
            uint32_t a[4][4], b[4][2];
            #pragma unroll
            for (int mi = 0; mi < 4; mi++) {
                uint32_t off = (uint32_t)((a_row + mi * 16) * 128 + ks * 32 + a_cb0);
                ldm_x4(a[mi][0], a[mi][1], a[mi][2], a[mi][3], abase + SWZ(off));
            }
            #pragma unroll
            for (int pr = 0; pr < 2; pr++) {
                uint32_t off = (uint32_t)((b_row + pr * 16) * 128 + ks * 32 + b_cb0);
                uint32_t r0, r1, r2, r3;
                ldm_x4(r0, r1, r2, r3, abase + OFF_B + SWZ(off));
                b[pr * 2 + 0][0] = r0; b[pr * 2 + 0][1] = r1;
                b[pr * 2 + 1][0] = r2; b[pr * 2 + 1][1] = r3;
            }
            #pragma unroll
            for (int mi = 0; mi < 4; mi++)
                #pragma unroll
                for (int ni = 0; ni < 4; ni++)
                    mma_f16(acc[mi][ni], a[mi], b[ni]);
        }

        if (lane == 0) mbar_arrive(eb0 + (g & 3) * 8);

        if ((g & 15) == 15) {
            int u = cta + (g >> 4) * GEMM_GRID;
            int z, mbk, nbk;
            tile_coord(u, z, mbk, nbk);
            const int m0 = mbk * 256, n0 = nbk * 128;
            const float* __restrict__ bias = (z == 0) ? bq : (z == 1) ? bk : bv;
            __half* __restrict__ out = g_qkvh[z];
            const int row_base = m0 + warp_m * 64 + (lane >> 2);
            const int col_loc = warp_n * 32 + (lane & 3) * 2;
            #pragma unroll
            for (int mi = 0; mi < 4; mi++) {
                #pragma unroll
                for (int ni = 0; ni < 4; ni++) {
                    const int col = col_loc + ni * 8;
                    const float b0 = __ldg(bias + n0 + col);
                    const float b1 = __ldg(bias + n0 + col + 1);
                    __half* p0 = out + (size_t)(row_base + mi * 16) * N_TOT + n0 + col;
                    __half* p1 = p0 + 8 * N_TOT;
                    *(__half2*)p0 = __floats2half2_rn(acc[mi][ni][0] + b0, acc[mi][ni][1] + b1);
                    *(__half2*)p1 = __floats2half2_rn(acc[mi][ni][2] + b0, acc[mi][ni][3] + b1);
                    #pragma unroll
                    for (int r = 0; r < 4; r++) acc[mi][ni][r] = 0.f;
                }
            }
            // publish tile completion
            __threadfence();
            __syncthreads();
            if (tid == 0) atomicAdd(&g_cnt[mbk], 1);
        }
    }

    // ===================== attention phase (work stealing, 2 tokens/warp) =====================
    __syncthreads();   // smem pipeline fully drained; dsm reused below
    while (true) {
        if (tid == 0) s_group = atomicAdd(&g_attn_ctr, 1);
        __syncthreads();
        const int w = s_group;
        if (w >= ATTN_GROUPS) break;
        const int mbk = w >> 3;                  // 8 groups of 32 tokens per m-block
        if (tid == 0) {
            while (ld_acq(&g_cnt[mbk]) < 24) __nanosleep(128);
        }
        __syncthreads();                          // flags visible to all warps
        const uint32_t tb0 = sbase + (uint32_t)wid * 12288;
        const uint32_t tb1 = tb0 + 6144;
        const int tok0 = w * 32 + wid;
        const int tok1 = tok0 + 16;
        attn_load(tb0, tok0, lane);
        cp_commit();
        attn_load(tb1, tok1, lane);
        cp_commit();
        cp_wait<1>();
        __syncwarp();
        attn_compute(tb0, tok0, lane, attn_out);
        cp_wait<0>();
        __syncwarp();
        attn_compute(tb1, tok1, lane, attn_out);
        __syncthreads();                          // warps done before next group fetch
    }
}

extern "C" void kernel_launch(void* const* d_in, const int* in_sizes, int n_in,
                              void* d_out, int out_size)
{
    const float* x  = (const float*)d_in[0];
    const float* Wq = (const float*)d_in[1];
    const float* bq = (const float*)d_in[2];
    const float* Wk = (const float*)d_in[3];
    const float* bk = (const float*)d_in[4];
    const float* Wv = (const float*)d_in[5];
    const float* bv = (const float*)d_in[6];
    float* out = (float*)d_out;

    convert_kernel<<<8192 + 3072, 256>>>(x, Wq, Wk, Wv);

    cudaFuncSetAttribute(qkv_fused, cudaFuncAttributeMaxDynamicSharedMemorySize, SMEM_DYN);
    qkv_fused<<<GEMM_GRID, GEMM_THREADS, SMEM_DYN>>>(bq, bk, bv, out);
}